// round 4
// baseline (speedup 1.0000x reference)
#include <cuda_runtime.h>

#define NN   500000
#define EE   8000000
#define DD   10
#define GG   5000
#define GPAD 16
#define BN_EPS 1e-5f

// ---- scratch (no allocations allowed) ----
__device__ __align__(16) float d_gacc[GG * GPAD];   // padded graph accumulator: 64B rows (2 clean sectors)
__device__ int   d_cnt[GG];
__device__ int   d_batch32[NN];                     // normalized int32 copy of batch
__device__ int   d_is64;                            // 1 if index buffers are int64-encoded
__device__ float d_stats[4 * 2 * DD];               // per-BN-stage {sum[10], sumsq[10]}
__device__ float d_bufs[5][GG * DD];                // 0:mean-pooled, 1:y1, 2:y2(res), 3:y3, 4:y4
__device__ float d_t[GG * DD];                      // pre-BN scratch

// ---- dtype detection: int64 indices < 2^31 have all odd 32-bit words == 0 ----
__global__ void k_detect(const int* __restrict__ ei) {
    if (threadIdx.x == 0 && blockIdx.x == 0) {
        int is64 = 1;
        #pragma unroll
        for (int k = 1; k < 64; k += 2)
            if (ei[k] != 0) { is64 = 0; break; }
        d_is64 = is64;
    }
}

// ---- zero all scratch (replayed every graph launch) ----
__global__ void k_zero() {
    int i = blockIdx.x * blockDim.x + threadIdx.x;
    if (i < GG * GPAD) d_gacc[i] = 0.f;
    if (i < GG)        d_cnt[i]  = 0;
    if (i < 4 * 2 * DD) d_stats[i] = 0.f;
}

// ---- per-graph node counts (batch sorted -> warp-aggregate) + int32 normalize ----
__global__ void k_count(const void* __restrict__ batch_raw) {
    int i = blockIdx.x * blockDim.x + threadIdx.x;
    if (i >= NN) return;                       // NN % 32 == 0: whole warps retire together
    int gid = d_is64 ? (int)((const long long*)batch_raw)[i]
                     : ((const int*)batch_raw)[i];
    d_batch32[i] = gid;
    unsigned mask = __match_any_sync(0xffffffffu, gid);
    int leader = __ffs(mask) - 1;
    if ((threadIdx.x & 31) == leader)
        atomicAdd(&d_cnt[gid], __popc(mask));
}

// ---- edge scatter: g[batch[dst]] += w * x[src]  (h[N,D] never materialized) ----
// Scalar f32 atomics only (vector fp32 RED traps on this target).
__global__ void __launch_bounds__(256) k_edge(const float* __restrict__ x,
                                              const void* __restrict__ ei_raw,
                                              const float* __restrict__ attr) {
    int e = blockIdx.x * blockDim.x + threadIdx.x;
    if (e >= EE) return;
    long long src, dst;
    if (d_is64) {
        const long long* ei = (const long long*)ei_raw;
        src = ei[e];
        dst = ei[(long long)EE + e];
    } else {
        const int* ei = (const int*)ei_raw;
        src = ei[e];
        dst = ei[EE + e];
    }
    float w = attr[e];
    int gid = __ldg(&d_batch32[dst]);

    const float2* xr = reinterpret_cast<const float2*>(x + (size_t)src * DD); // 8B-aligned (stride 40B)
    float2 p0 = xr[0], p1 = xr[1], p2 = xr[2], p3 = xr[3], p4 = xr[4];

    float* row = d_gacc + (size_t)gid * GPAD;
    atomicAdd(row + 0, p0.x * w);
    atomicAdd(row + 1, p0.y * w);
    atomicAdd(row + 2, p1.x * w);
    atomicAdd(row + 3, p1.y * w);
    atomicAdd(row + 4, p2.x * w);
    atomicAdd(row + 5, p2.y * w);
    atomicAdd(row + 6, p3.x * w);
    atomicAdd(row + 7, p3.y * w);
    atomicAdd(row + 8, p4.x * w);
    atomicAdd(row + 9, p4.y * w);
}

// ---- mean pool: bufs[0] = gacc / max(cnt,1) ----
__global__ void k_mean() {
    int i = blockIdx.x * blockDim.x + threadIdx.x;
    if (i >= GG * DD) return;
    int g = i / DD, d = i - g * DD;
    int c = d_cnt[g]; if (c < 1) c = 1;
    d_bufs[0][i] = d_gacc[g * GPAD + d] / (float)c;
}

// ---- linear [G,10]@[10,10]^T + bias, with per-feature sum/sumsq for BN ----
__global__ void __launch_bounds__(256) k_mm_stats(int inbuf, int stage,
                                                  const float* __restrict__ W,
                                                  const float* __restrict__ b) {
    __shared__ float sW[DD * DD], sb[DD], ssum[DD], ssq[DD];
    int tid = threadIdx.x;
    if (tid < DD * DD) sW[tid] = W[tid];
    if (tid < DD) { sb[tid] = b[tid]; ssum[tid] = 0.f; ssq[tid] = 0.f; }
    __syncthreads();

    int g = blockIdx.x * blockDim.x + tid;
    float out[DD];
    if (g < GG) {
        float in[DD];
        #pragma unroll
        for (int d = 0; d < DD; d++) in[d] = d_bufs[inbuf][g * DD + d];
        #pragma unroll
        for (int o = 0; o < DD; o++) {
            float a = sb[o];
            #pragma unroll
            for (int d = 0; d < DD; d++) a = fmaf(sW[o * DD + d], in[d], a);
            out[o] = a;
            d_t[g * DD + o] = a;
        }
    } else {
        #pragma unroll
        for (int o = 0; o < DD; o++) out[o] = 0.f;
    }
    #pragma unroll
    for (int o = 0; o < DD; o++) {
        atomicAdd(&ssum[o], out[o]);
        atomicAdd(&ssq[o],  out[o] * out[o]);
    }
    __syncthreads();
    if (tid < DD) {
        atomicAdd(&d_stats[stage * 2 * DD + tid],      ssum[tid]);
        atomicAdd(&d_stats[stage * 2 * DD + DD + tid], ssq[tid]);
    }
}

// ---- batchnorm (training stats, biased var) + optional residual + relu ----
__global__ void k_bn(int stage, int outbuf, int resbuf,
                     const float* __restrict__ gamma,
                     const float* __restrict__ beta) {
    int i = blockIdx.x * blockDim.x + threadIdx.x;
    if (i >= GG * DD) return;
    int o = i % DD;
    float s  = d_stats[stage * 2 * DD + o];
    float sq = d_stats[stage * 2 * DD + DD + o];
    float m = s * (1.f / GG);
    float v = sq * (1.f / GG) - m * m;
    float val = gamma[o] * (d_t[i] - m) * rsqrtf(v + BN_EPS) + beta[o];
    if (resbuf >= 0) val += d_bufs[resbuf][i];
    d_bufs[outbuf][i] = fmaxf(val, 0.f);
}

// ---- final projection to [G,1] ----
__global__ void k_final(const float* __restrict__ W, const float* __restrict__ b,
                        float* __restrict__ out) {
    int g = blockIdx.x * blockDim.x + threadIdx.x;
    if (g >= GG) return;
    float a = b[0];
    #pragma unroll
    for (int d = 0; d < DD; d++) a = fmaf(d_bufs[4][g * DD + d], W[d], a);
    out[g] = a;
}

extern "C" void kernel_launch(void* const* d_in, const int* in_sizes, int n_in,
                              void* d_out, int out_size) {
    const float* x     = (const float*)d_in[0];
    const void*  ei    = d_in[1];
    const float* attr  = (const float*)d_in[2];
    const void*  batch = d_in[3];
    const float* fc1_w  = (const float*)d_in[4],  *fc1_b  = (const float*)d_in[5];
    const float* fc2_w  = (const float*)d_in[6],  *fc2_b  = (const float*)d_in[7];
    const float* rfc1_w = (const float*)d_in[8],  *rfc1_b = (const float*)d_in[9];
    const float* rfc2_w = (const float*)d_in[10], *rfc2_b = (const float*)d_in[11];
    const float* fco_w  = (const float*)d_in[12], *fco_b  = (const float*)d_in[13];
    const float* bn1_g  = (const float*)d_in[14], *bn1_b  = (const float*)d_in[15];
    const float* bn2_g  = (const float*)d_in[16], *bn2_b  = (const float*)d_in[17];
    const float* rbn1_g = (const float*)d_in[18], *rbn1_b = (const float*)d_in[19];
    const float* rbn2_g = (const float*)d_in[20], *rbn2_b = (const float*)d_in[21];
    float* out = (float*)d_out;

    k_detect<<<1, 32>>>((const int*)ei);
    k_zero <<<(GG * GPAD + 255) / 256, 256>>>();
    k_count<<<(NN + 255) / 256, 256>>>(batch);
    k_edge <<<EE / 256, 256>>>(x, ei, attr);
    k_mean <<<(GG * DD + 255) / 256, 256>>>();

    k_mm_stats<<<(GG + 255) / 256, 256>>>(0, 0, fc1_w, fc1_b);
    k_bn      <<<(GG * DD + 255) / 256, 256>>>(0, 1, -1, bn1_g, bn1_b);
    k_mm_stats<<<(GG + 255) / 256, 256>>>(1, 1, fc2_w, fc2_b);
    k_bn      <<<(GG * DD + 255) / 256, 256>>>(1, 2, -1, bn2_g, bn2_b);
    k_mm_stats<<<(GG + 255) / 256, 256>>>(2, 2, rfc1_w, rfc1_b);
    k_bn      <<<(GG * DD + 255) / 256, 256>>>(2, 3, -1, rbn1_g, rbn1_b);
    k_mm_stats<<<(GG + 255) / 256, 256>>>(3, 3, rfc2_w, rfc2_b);
    k_bn      <<<(GG * DD + 255) / 256, 256>>>(3, 4, 2, rbn2_g, rbn2_b);

    k_final<<<(GG + 255) / 256, 256>>>(fco_w, fco_b, out);
}

// round 5
// speedup vs baseline: 1.4871x; 1.4871x over previous
#include <cuda_runtime.h>

#define NN   500000
#define EE   8000000
#define DD   10
#define GG   5000
#define SROW 11                  // smem row stride: gcd(11,32)=1 -> all 32 banks used
#define BN_EPS 1e-5f
#define NBLK 148

// ---- scratch (no allocations allowed) ----
__device__ float d_gacc[GG * DD];
__device__ int   d_cnt[GG];
__device__ int   d_batch32[NN];
__device__ int   d_is64;
__device__ float d_bufs[5][GG * DD];   // 0:pooled, 1:y1, 2:y2(res), 3:y3, 4:y4
__device__ float d_t[GG * DD];         // pre-BN scratch (intra-k_head)

// ---- prep: dtype detect (int64 indices < 2^31 => odd 32-bit words all zero) + zero scratch ----
__global__ void k_prep(const int* __restrict__ ei) {
    int i = blockIdx.x * blockDim.x + threadIdx.x;
    if (i == 0) {
        int is64 = 1;
        #pragma unroll
        for (int k = 1; k < 64; k += 2)
            if (ei[k] != 0) { is64 = 0; break; }
        d_is64 = is64;
    }
    if (i < GG * DD) d_gacc[i] = 0.f;
    if (i < GG)      d_cnt[i]  = 0;
}

// ---- per-graph node counts (batch sorted -> warp-aggregate) + int32 normalize ----
__global__ void k_count(const void* __restrict__ batch_raw) {
    int i = blockIdx.x * blockDim.x + threadIdx.x;
    if (i >= NN) return;                 // NN % 32 == 0: whole warps retire together
    int gid = d_is64 ? (int)((const long long*)batch_raw)[i]
                     : ((const int*)batch_raw)[i];
    d_batch32[i] = gid;
    unsigned mask = __match_any_sync(0xffffffffu, gid);
    if ((threadIdx.x & 31) == (__ffs(mask) - 1))
        atomicAdd(&d_cnt[gid], __popc(mask));
}

// ---- edge scatter with SMEM-privatized per-block accumulator ----
// g[batch[dst]] += w * x[src]; 10 shared atomics/edge, one 50k-RED flush per block.
__global__ void __launch_bounds__(1024, 1) k_edge(const float* __restrict__ x,
                                                  const void* __restrict__ ei_raw,
                                                  const float* __restrict__ attr) {
    extern __shared__ float sg[];        // GG * SROW floats = 220,000 B
    const bool is64 = (d_is64 != 0);
    for (int i = threadIdx.x; i < GG * SROW; i += 1024) sg[i] = 0.f;
    __syncthreads();

    const int chunk = (EE + NBLK - 1) / NBLK;
    const int e0 = blockIdx.x * chunk;
    const int e1 = (e0 + chunk < EE) ? e0 + chunk : EE;

    if (!is64) {
        const int* ei = (const int*)ei_raw;
        for (int e = e0 + threadIdx.x; e < e1; e += 1024) {
            int src = ei[e], dst = ei[EE + e];
            float w = attr[e];
            int gid = __ldg(&d_batch32[dst]);
            const float2* xr = reinterpret_cast<const float2*>(x + (size_t)src * DD);
            float2 p0 = xr[0], p1 = xr[1], p2 = xr[2], p3 = xr[3], p4 = xr[4];
            float* r = sg + gid * SROW;
            atomicAdd(r + 0, p0.x * w); atomicAdd(r + 1, p0.y * w);
            atomicAdd(r + 2, p1.x * w); atomicAdd(r + 3, p1.y * w);
            atomicAdd(r + 4, p2.x * w); atomicAdd(r + 5, p2.y * w);
            atomicAdd(r + 6, p3.x * w); atomicAdd(r + 7, p3.y * w);
            atomicAdd(r + 8, p4.x * w); atomicAdd(r + 9, p4.y * w);
        }
    } else {
        const long long* ei = (const long long*)ei_raw;
        for (int e = e0 + threadIdx.x; e < e1; e += 1024) {
            long long src = ei[e], dst = ei[(long long)EE + e];
            float w = attr[e];
            int gid = __ldg(&d_batch32[dst]);
            const float2* xr = reinterpret_cast<const float2*>(x + (size_t)src * DD);
            float2 p0 = xr[0], p1 = xr[1], p2 = xr[2], p3 = xr[3], p4 = xr[4];
            float* r = sg + gid * SROW;
            atomicAdd(r + 0, p0.x * w); atomicAdd(r + 1, p0.y * w);
            atomicAdd(r + 2, p1.x * w); atomicAdd(r + 3, p1.y * w);
            atomicAdd(r + 4, p2.x * w); atomicAdd(r + 5, p2.y * w);
            atomicAdd(r + 6, p3.x * w); atomicAdd(r + 7, p3.y * w);
            atomicAdd(r + 8, p4.x * w); atomicAdd(r + 9, p4.y * w);
        }
    }
    __syncthreads();
    // flush private accumulator: 50k global REDs per block
    for (int i = threadIdx.x; i < GG * DD; i += 1024) {
        int g = i / DD, d = i - g * DD;
        atomicAdd(&d_gacc[i], sg[g * SROW + d]);
    }
}

// ---- entire MLP head in ONE single-block kernel (grid=1, block=512) ----
__global__ void __launch_bounds__(512, 1) k_head(
    const float* __restrict__ fc1_w,  const float* __restrict__ fc1_b,
    const float* __restrict__ fc2_w,  const float* __restrict__ fc2_b,
    const float* __restrict__ rfc1_w, const float* __restrict__ rfc1_b,
    const float* __restrict__ rfc2_w, const float* __restrict__ rfc2_b,
    const float* __restrict__ fco_w,  const float* __restrict__ fco_b,
    const float* __restrict__ bn1_g,  const float* __restrict__ bn1_b,
    const float* __restrict__ bn2_g,  const float* __restrict__ bn2_b,
    const float* __restrict__ rbn1_g, const float* __restrict__ rbn1_b,
    const float* __restrict__ rbn2_g, const float* __restrict__ rbn2_b,
    float* __restrict__ out)
{
    __shared__ float sW[DD * DD], sb[DD], sgm[DD], sbt[DD];
    __shared__ float swred[16][2 * DD];   // per-warp partial {sum,sumsq}
    __shared__ float sstat[2 * DD];
    const int tid = threadIdx.x;
    const int wid = tid >> 5, lid = tid & 31;

    // mean pool into bufs[0]
    for (int i = tid; i < GG * DD; i += 512) {
        int g = i / DD;
        int c = d_cnt[g]; if (c < 1) c = 1;
        d_bufs[0][i] = d_gacc[i] / (float)c;
    }
    __syncthreads();

    const float* Ws[4]  = {fc1_w, fc2_w, rfc1_w, rfc2_w};
    const float* bs[4]  = {fc1_b, fc2_b, rfc1_b, rfc2_b};
    const float* gms[4] = {bn1_g, bn2_g, rbn1_g, rbn2_g};
    const float* bts[4] = {bn1_b, bn2_b, rbn1_b, rbn2_b};

    #pragma unroll 1
    for (int s = 0; s < 4; s++) {
        const float* inb = d_bufs[s];
        float*       outb = d_bufs[s + 1];
        const float* resb = (s == 3) ? d_bufs[2] : nullptr;

        if (tid < DD * DD) sW[tid] = Ws[s][tid];
        if (tid < DD) { sb[tid] = bs[s][tid]; sgm[tid] = gms[s][tid]; sbt[tid] = bts[s][tid]; }
        __syncthreads();

        float lsum[DD], lsq[DD];
        #pragma unroll
        for (int o = 0; o < DD; o++) { lsum[o] = 0.f; lsq[o] = 0.f; }

        for (int g = tid; g < GG; g += 512) {
            float in[DD];
            #pragma unroll
            for (int d = 0; d < DD; d++) in[d] = inb[g * DD + d];
            #pragma unroll
            for (int o = 0; o < DD; o++) {
                float a = sb[o];
                #pragma unroll
                for (int d = 0; d < DD; d++) a = fmaf(sW[o * DD + d], in[d], a);
                d_t[g * DD + o] = a;
                lsum[o] += a;
                lsq[o]  = fmaf(a, a, lsq[o]);
            }
        }
        // warp tree-reduce 20 stats
        #pragma unroll
        for (int o = 0; o < DD; o++) {
            #pragma unroll
            for (int off = 16; off > 0; off >>= 1) {
                lsum[o] += __shfl_xor_sync(0xffffffffu, lsum[o], off);
                lsq[o]  += __shfl_xor_sync(0xffffffffu, lsq[o],  off);
            }
        }
        if (lid < DD)           swred[wid][lid]      = lsum[lid];
        else if (lid < 2 * DD)  swred[wid][lid]      = lsq[lid - DD];
        __syncthreads();
        if (tid < 2 * DD) {
            float a = 0.f;
            #pragma unroll
            for (int w = 0; w < 16; w++) a += swred[w][tid];
            sstat[tid] = a;
        }
        __syncthreads();

        for (int g = tid; g < GG; g += 512) {
            #pragma unroll
            for (int o = 0; o < DD; o++) {
                float m = sstat[o] * (1.f / GG);
                float v = sstat[DD + o] * (1.f / GG) - m * m;
                float val = sgm[o] * (d_t[g * DD + o] - m) * rsqrtf(v + BN_EPS) + sbt[o];
                if (resb) val += resb[g * DD + o];
                outb[g * DD + o] = fmaxf(val, 0.f);
            }
        }
        __syncthreads();
    }

    // final projection [G,1]
    if (tid < DD) sW[tid] = fco_w[tid];
    if (tid == 0) sb[0] = fco_b[0];
    __syncthreads();
    for (int g = tid; g < GG; g += 512) {
        float a = sb[0];
        #pragma unroll
        for (int d = 0; d < DD; d++) a = fmaf(d_bufs[4][g * DD + d], sW[d], a);
        out[g] = a;
    }
}

extern "C" void kernel_launch(void* const* d_in, const int* in_sizes, int n_in,
                              void* d_out, int out_size) {
    const float* x     = (const float*)d_in[0];
    const void*  ei    = d_in[1];
    const float* attr  = (const float*)d_in[2];
    const void*  batch = d_in[3];
    const float* fc1_w  = (const float*)d_in[4],  *fc1_b  = (const float*)d_in[5];
    const float* fc2_w  = (const float*)d_in[6],  *fc2_b  = (const float*)d_in[7];
    const float* rfc1_w = (const float*)d_in[8],  *rfc1_b = (const float*)d_in[9];
    const float* rfc2_w = (const float*)d_in[10], *rfc2_b = (const float*)d_in[11];
    const float* fco_w  = (const float*)d_in[12], *fco_b  = (const float*)d_in[13];
    const float* bn1_g  = (const float*)d_in[14], *bn1_b  = (const float*)d_in[15];
    const float* bn2_g  = (const float*)d_in[16], *bn2_b  = (const float*)d_in[17];
    const float* rbn1_g = (const float*)d_in[18], *rbn1_b = (const float*)d_in[19];
    const float* rbn2_g = (const float*)d_in[20], *rbn2_b = (const float*)d_in[21];
    float* out = (float*)d_out;

    static const int SMEM_EDGE = GG * SROW * (int)sizeof(float);   // 220,000 B
    cudaFuncSetAttribute(k_edge, cudaFuncAttributeMaxDynamicSharedMemorySize, SMEM_EDGE);

    k_prep <<<(GG * DD + 1023) / 1024, 1024>>>((const int*)ei);
    k_count<<<(NN + 255) / 256, 256>>>(batch);
    k_edge <<<NBLK, 1024, SMEM_EDGE>>>(x, ei, attr);
    k_head <<<1, 512>>>(fc1_w, fc1_b, fc2_w, fc2_b, rfc1_w, rfc1_b, rfc2_w, rfc2_b,
                        fco_w, fco_b, bn1_g, bn1_b, bn2_g, bn2_b,
                        rbn1_g, rbn1_b, rbn2_g, rbn2_b, out);
}

// round 9
// speedup vs baseline: 2.7363x; 1.8400x over previous
#include <cuda_runtime.h>

#define NN   500000
#define EE   8000000
#define DD   10
#define GG   5000
#define SROW 11                  // smem row stride: gcd(11,32)=1 -> all 32 banks used
#define BN_EPS 1e-5f
#define NBLK 148                 // edge-scatter blocks
#define NHB  20                  // head blocks
#define NHT  256                 // head threads/block

// ---- scratch (no allocations allowed) ----
__device__ float d_gacc[GG * DD];
__device__ int   d_batch32[NN];
__device__ int   d_is64;
__device__ float d_stats[4 * 2 * DD];   // per-stage {sum[10], sumsq[10]}
__device__ float d_t[GG * DD];          // pre-BN activations (reused across stages)
__device__ float d_res[GG * DD];        // residual (y2)

// ---- prep: dtype detect, zero scratch, batch->int32 (NO counting -> no race) ----
__global__ void k_pc(const int* __restrict__ ei, const void* __restrict__ batch_raw) {
    __shared__ int s_is64;
    if (threadIdx.x == 0) {
        int is64 = 1;
        #pragma unroll
        for (int k = 1; k < 64; k += 2)
            if (ei[k] != 0) { is64 = 0; break; }
        s_is64 = is64;
        if (blockIdx.x == 0) d_is64 = is64;
    }
    __syncthreads();
    int i = blockIdx.x * blockDim.x + threadIdx.x;
    if (i < GG * DD)    d_gacc[i]  = 0.f;   // written only by later k_edge: race-free
    if (i < 4 * 2 * DD) d_stats[i] = 0.f;   // written only by later k_stage: race-free
    if (i >= NN) return;
    d_batch32[i] = s_is64 ? (int)((const long long*)batch_raw)[i]
                          : ((const int*)batch_raw)[i];
}

// ---- edge scatter with SMEM-privatized per-block accumulator ----
__global__ void __launch_bounds__(1024, 1) k_edge(const float* __restrict__ x,
                                                  const void* __restrict__ ei_raw,
                                                  const float* __restrict__ attr) {
    extern __shared__ float sg[];          // GG * SROW floats = 220,000 B
    const bool is64 = (d_is64 != 0);
    for (int i = threadIdx.x; i < GG * SROW; i += 1024) sg[i] = 0.f;
    __syncthreads();

    const int chunk = (EE + NBLK - 1) / NBLK;
    const int e0 = blockIdx.x * chunk;
    const int e1 = (e0 + chunk < EE) ? e0 + chunk : EE;

    if (!is64) {
        const int* ei = (const int*)ei_raw;
        for (int e = e0 + threadIdx.x; e < e1; e += 1024) {
            int src = ei[e], dst = ei[EE + e];
            float w = attr[e];
            int gid = __ldg(&d_batch32[dst]);
            const float2* xr = reinterpret_cast<const float2*>(x + (size_t)src * DD);
            float2 p0 = xr[0], p1 = xr[1], p2 = xr[2], p3 = xr[3], p4 = xr[4];
            float* r = sg + gid * SROW;
            atomicAdd(r + 0, p0.x * w); atomicAdd(r + 1, p0.y * w);
            atomicAdd(r + 2, p1.x * w); atomicAdd(r + 3, p1.y * w);
            atomicAdd(r + 4, p2.x * w); atomicAdd(r + 5, p2.y * w);
            atomicAdd(r + 6, p3.x * w); atomicAdd(r + 7, p3.y * w);
            atomicAdd(r + 8, p4.x * w); atomicAdd(r + 9, p4.y * w);
        }
    } else {
        const long long* ei = (const long long*)ei_raw;
        for (int e = e0 + threadIdx.x; e < e1; e += 1024) {
            long long src = ei[e], dst = ei[(long long)EE + e];
            float w = attr[e];
            int gid = __ldg(&d_batch32[dst]);
            const float2* xr = reinterpret_cast<const float2*>(x + (size_t)src * DD);
            float2 p0 = xr[0], p1 = xr[1], p2 = xr[2], p3 = xr[3], p4 = xr[4];
            float* r = sg + gid * SROW;
            atomicAdd(r + 0, p0.x * w); atomicAdd(r + 1, p0.y * w);
            atomicAdd(r + 2, p1.x * w); atomicAdd(r + 3, p1.y * w);
            atomicAdd(r + 4, p2.x * w); atomicAdd(r + 5, p2.y * w);
            atomicAdd(r + 6, p3.x * w); atomicAdd(r + 7, p3.y * w);
            atomicAdd(r + 8, p4.x * w); atomicAdd(r + 9, p4.y * w);
        }
    }
    __syncthreads();
    for (int i = threadIdx.x; i < GG * DD; i += 1024) {
        int g = i / DD, d = i - g * DD;
        atomicAdd(&d_gacc[i], sg[g * SROW + d]);
    }
}

// ---- MLP head stage kernel (launched 5x; kernel boundaries = global sync) ----
// s=0: y=pool (count via binary search); t=fc1(y);  stats0
// s=1: y=relu(bn0(t));                   t=fc2(y);  stats1
// s=2: y=relu(bn1(t)); res=y;            t=rfc1(y); stats2
// s=3: y=relu(bn2(t));                   t=rfc2(y); stats3
// s=4: y=relu(bn3(t)+res);               out=fco(y)
__global__ void __launch_bounds__(NHT, 1) k_stage(
    int s,
    const float* __restrict__ W,   const float* __restrict__ bias,   // this stage's linear (s=4: fco)
    const float* __restrict__ gpr, const float* __restrict__ bpr,    // BN params of stage s-1 (s>=1)
    float* __restrict__ outp)                                        // s=4 only
{
    __shared__ float sW[DD * DD], sb[DD], sgm[DD], sbt[DD], sst[2 * DD];
    __shared__ float sred[NHT / 32][2 * DD];
    const int tid = threadIdx.x;
    const int wid = tid >> 5, lid = tid & 31;
    const int g = blockIdx.x * NHT + tid;
    const bool act = (g < GG);

    if (s < 4) {
        if (tid < DD * DD) sW[tid] = W[tid];
        if (tid < DD) sb[tid] = bias[tid];
    } else {
        if (tid < DD) sW[tid] = W[tid];
        if (tid == 0) sb[0] = bias[0];
    }
    if (s >= 1) {
        if (tid < DD) { sgm[tid] = gpr[tid]; sbt[tid] = bpr[tid]; }
        if (tid < 2 * DD) sst[tid] = d_stats[(s - 1) * 2 * DD + tid];
    }
    __syncthreads();

    // ---- entry: build y ----
    float y[DD];
    if (s == 0) {
        if (act) {
            // count of graph g in sorted d_batch32 via two binary searches
            int lo = 0, hi = NN;
            while (lo < hi) { int mid = (lo + hi) >> 1; if (d_batch32[mid] <  g) lo = mid + 1; else hi = mid; }
            int lb = lo;
            lo = 0; hi = NN;
            while (lo < hi) { int mid = (lo + hi) >> 1; if (d_batch32[mid] <= g) lo = mid + 1; else hi = mid; }
            int c = lo - lb; if (c < 1) c = 1;
            float inv = 1.f / (float)c;
            #pragma unroll
            for (int d = 0; d < DD; d++) y[d] = d_gacc[g * DD + d] * inv;
        } else {
            #pragma unroll
            for (int d = 0; d < DD; d++) y[d] = 0.f;
        }
    } else {
        #pragma unroll
        for (int o = 0; o < DD; o++) {
            float t = act ? d_t[g * DD + o] : 0.f;
            float m = sst[o] * (1.f / GG);
            float q = sst[DD + o] * (1.f / GG);
            float v = q - m * m;
            float val = sgm[o] * (t - m) * rsqrtf(v + BN_EPS) + sbt[o];
            if (s == 4 && act) val += d_res[g * DD + o];
            y[o] = fmaxf(val, 0.f);
        }
        if (s == 2 && act) {
            #pragma unroll
            for (int o = 0; o < DD; o++) d_res[g * DD + o] = y[o];
        }
    }

    // ---- body ----
    if (s == 4) {
        if (act) {
            float a = sb[0];
            #pragma unroll
            for (int d = 0; d < DD; d++) a = fmaf(y[d], sW[d], a);
            outp[g] = a;
        }
        return;
    }

    float o_[DD];
    #pragma unroll
    for (int o = 0; o < DD; o++) {
        float a = sb[o];
        #pragma unroll
        for (int d = 0; d < DD; d++) a = fmaf(sW[o * DD + d], y[d], a);
        o_[o] = act ? a : 0.f;
        if (act) d_t[g * DD + o] = a;
    }

    // ---- stats block-reduce -> global atomics ----
    float ls[DD], lq[DD];
    #pragma unroll
    for (int o = 0; o < DD; o++) {
        ls[o] = o_[o]; lq[o] = o_[o] * o_[o];
        #pragma unroll
        for (int off = 16; off > 0; off >>= 1) {
            ls[o] += __shfl_xor_sync(0xffffffffu, ls[o], off);
            lq[o] += __shfl_xor_sync(0xffffffffu, lq[o], off);
        }
    }
    if (lid < DD)          sred[wid][lid] = ls[lid];
    else if (lid < 2 * DD) sred[wid][lid] = lq[lid - DD];
    __syncthreads();
    if (tid < 2 * DD) {
        float a = 0.f;
        #pragma unroll
        for (int w = 0; w < NHT / 32; w++) a += sred[w][tid];
        atomicAdd(&d_stats[s * 2 * DD + tid], a);
    }
}

extern "C" void kernel_launch(void* const* d_in, const int* in_sizes, int n_in,
                              void* d_out, int out_size) {
    const float* x     = (const float*)d_in[0];
    const void*  ei    = d_in[1];
    const float* attr  = (const float*)d_in[2];
    const void*  batch = d_in[3];
    const float* fc1_w  = (const float*)d_in[4],  *fc1_b  = (const float*)d_in[5];
    const float* fc2_w  = (const float*)d_in[6],  *fc2_b  = (const float*)d_in[7];
    const float* rfc1_w = (const float*)d_in[8],  *rfc1_b = (const float*)d_in[9];
    const float* rfc2_w = (const float*)d_in[10], *rfc2_b = (const float*)d_in[11];
    const float* fco_w  = (const float*)d_in[12], *fco_b  = (const float*)d_in[13];
    const float* bn1_g  = (const float*)d_in[14], *bn1_b  = (const float*)d_in[15];
    const float* bn2_g  = (const float*)d_in[16], *bn2_b  = (const float*)d_in[17];
    const float* rbn1_g = (const float*)d_in[18], *rbn1_b = (const float*)d_in[19];
    const float* rbn2_g = (const float*)d_in[20], *rbn2_b = (const float*)d_in[21];
    float* out = (float*)d_out;

    static const int SMEM_EDGE = GG * SROW * (int)sizeof(float);   // 220,000 B
    cudaFuncSetAttribute(k_edge, cudaFuncAttributeMaxDynamicSharedMemorySize, SMEM_EDGE);

    k_pc   <<<(NN + 255) / 256, 256>>>((const int*)ei, batch);
    k_edge <<<NBLK, 1024, SMEM_EDGE>>>(x, ei, attr);

    k_stage<<<NHB, NHT>>>(0, fc1_w,  fc1_b,  nullptr, nullptr, nullptr);
    k_stage<<<NHB, NHT>>>(1, fc2_w,  fc2_b,  bn1_g,  bn1_b,  nullptr);
    k_stage<<<NHB, NHT>>>(2, rfc1_w, rfc1_b, bn2_g,  bn2_b,  nullptr);
    k_stage<<<NHB, NHT>>>(3, rfc2_w, rfc2_b, rbn1_g, rbn1_b, nullptr);
    k_stage<<<NHB, NHT>>>(4, fco_w,  fco_b,  rbn2_g, rbn2_b, out);
}